// round 5
// baseline (speedup 1.0000x reference)
#include <cuda_runtime.h>
#include <cuda_bf16.h>
#include <math.h>
#include <stdint.h>

#define BATCH   64
#define CH      96
#define HW      12544
#define MTOK    6
#define HEADS   4
#define RQ      24
#define DMODEL  192
#define QDIM    384
#define SCALE_F 0.10206207261596575f  // 96^-0.5
#define SPLITS  14
#define CHUNK   896         // HW / SPLITS
#define TILE    128
#define TILES_PER 7         // CHUNK / TILE
#define XSTR    136         // bf16 elems per X row (128 + 8 pad)
#define FSTR    132         // fp32 elems per staging row (128 + 4 pad)
#define QSTR    104         // bf16 elems per Q row (96 + 8 pad)
#define OSTR    100         // padded O row stride (floats) in reduce buffer
#define WSTR    3208        // per-warp reduce-buffer stride (floats)

// smem byte offsets (attn kernel); sOr overlays the pipeline buffers
#define OFF_XF   0
#define OFF_Q    50688
#define OFF_X    57344       // 50688 + 6656
#define OFF_MAX  102656      // = 8*WSTR*4 (end of sOr region)
#define OFF_SUM  103680
#define SMEM_TOT 104704

// scratch (device globals: no allocation allowed)
__device__ float g_Qp[4 * BATCH * RQ * CH];
__device__ float g_Mx[BATCH * SPLITS * RQ];
__device__ float g_Lx[BATCH * SPLITS * RQ];
__device__ float g_Ox[BATCH * SPLITS * RQ * CH];

// ---------------------------------------------------------------------------
// PTX helpers
// ---------------------------------------------------------------------------
__device__ __forceinline__ uint32_t smem_u32(const void* p) {
    return (uint32_t)__cvta_generic_to_shared(p);
}
__device__ __forceinline__ void ldm_x4(uint32_t& r0, uint32_t& r1, uint32_t& r2,
                                       uint32_t& r3, uint32_t addr) {
    asm volatile("ldmatrix.sync.aligned.m8n8.x4.shared.b16 {%0,%1,%2,%3}, [%4];"
                 : "=r"(r0), "=r"(r1), "=r"(r2), "=r"(r3) : "r"(addr));
}
__device__ __forceinline__ void ldm_x4_t(uint32_t& r0, uint32_t& r1, uint32_t& r2,
                                         uint32_t& r3, uint32_t addr) {
    asm volatile("ldmatrix.sync.aligned.m8n8.x4.trans.shared.b16 {%0,%1,%2,%3}, [%4];"
                 : "=r"(r0), "=r"(r1), "=r"(r2), "=r"(r3) : "r"(addr));
}
__device__ __forceinline__ void mma16816(float* c, const uint32_t* a,
                                         uint32_t b0, uint32_t b1) {
    asm volatile("mma.sync.aligned.m16n8k16.row.col.f32.bf16.bf16.f32 "
                 "{%0,%1,%2,%3}, {%4,%5,%6,%7}, {%8,%9}, {%0,%1,%2,%3};"
                 : "+f"(c[0]), "+f"(c[1]), "+f"(c[2]), "+f"(c[3])
                 : "r"(a[0]), "r"(a[1]), "r"(a[2]), "r"(a[3]), "r"(b0), "r"(b1));
}
__device__ __forceinline__ void cpasync16(uint32_t dst, const void* src) {
    asm volatile("cp.async.cg.shared.global [%0], [%1], 16;" :: "r"(dst), "l"(src));
}
#define CP_COMMIT() asm volatile("cp.async.commit_group;" ::: "memory")
#define CP_WAIT0()  asm volatile("cp.async.wait_group 0;" ::: "memory")

__device__ __forceinline__ uint32_t pack_bf16(float a, float b) {
    __nv_bfloat162 h2 = __floats2bfloat162_rn(a, b);
    return *(uint32_t*)&h2;
}

// ---------------------------------------------------------------------------
// Kernel 1: Q projection, split-k x4. grid (BATCH, 4), 384 threads.
// ---------------------------------------------------------------------------
__global__ __launch_bounds__(QDIM) void qproj_kernel(
    const float* __restrict__ z, const float* __restrict__ Wq,
    const float* __restrict__ bq)
{
    __shared__ float sz[MTOK * 48];
    const int b = blockIdx.x, kq = blockIdx.y, col = threadIdx.x;
    for (int i = col; i < MTOK * 48; i += QDIM) {
        const int m = i / 48, k = i - m * 48;
        sz[i] = z[b * MTOK * DMODEL + m * DMODEL + kq * 48 + k];
    }
    __syncthreads();

    float acc[MTOK];
    const float b0 = (kq == 0) ? bq[col] : 0.f;
    #pragma unroll
    for (int m = 0; m < MTOK; ++m) acc[m] = b0;

    const float* Wqp = Wq + (size_t)(kq * 48) * QDIM + col;
    #pragma unroll
    for (int k = 0; k < 48; ++k) {
        const float w = __ldg(Wqp + k * QDIM);
        #pragma unroll
        for (int m = 0; m < MTOK; ++m)
            acc[m] = fmaf(sz[m * 48 + k], w, acc[m]);
    }
    const int h = col / CH, c = col - h * CH;
    #pragma unroll
    for (int m = 0; m < MTOK; ++m)
        g_Qp[kq * (BATCH * RQ * CH) + (b * RQ + h * MTOK + m) * CH + c] = acc[m] * SCALE_F;
}

// ---------------------------------------------------------------------------
// Kernel 2: bf16 TC flash attention, P kept in registers (S->A frag identity).
// grid (SPLITS, BATCH), 256 threads = 8 warps, 1 CTA/SM.
// Warp w owns spatial cols [16w, 16w+16) as its private PV k-slice and
// accumulates a partial O[32 x 96]; partials summed in epilogue.
// ---------------------------------------------------------------------------
__global__ __launch_bounds__(256, 1) void attn_partial_kernel(const float* __restrict__ x)
{
    extern __shared__ char smem[];
    float*         sXf  = (float*)(smem + OFF_XF);           // 96*132*4 = 50688
    __nv_bfloat16* sQ   = (__nv_bfloat16*)(smem + OFF_Q);    // 32*104*2 = 6656
    __nv_bfloat16* sX   = (__nv_bfloat16*)(smem + OFF_X);    // 96*136*2 = 26112
    float*         sOr  = (float*)smem;                      // epilogue overlay
    float*         sMax = (float*)(smem + OFF_MAX);
    float*         sSum = (float*)(smem + OFF_SUM);

    const int b = blockIdx.y, s = blockIdx.x;
    const int tid = threadIdx.x, lane = tid & 31, warp = tid >> 5;
    const int g = lane >> 2, tig = lane & 3;

    const uint32_t uQ  = smem_u32(sQ);
    const uint32_t uX  = smem_u32(sX);
    const uint32_t uXf = smem_u32(sXf);

    const float* xb = x + (size_t)b * CH * HW + (size_t)s * CHUNK;

    // ---- issue cp.async for tile 0 ----
    #pragma unroll
    for (int r = 0; r < 12; ++r) {
        const int i = tid + 256 * r;
        const int c = i >> 5, n4 = (i & 31) << 2;
        cpasync16(uXf + (c * FSTR + n4) * 4, xb + (size_t)c * HW + n4);
    }
    CP_COMMIT();

    // ---- stage Q (sum of 4 split-k partials -> bf16), rows 24..31 zero ----
    for (int i = tid; i < 32 * CH; i += 256) {
        const int r = i / CH, c = i - r * CH;
        float v = 0.f;
        if (r < RQ) {
            const int idx = (b * RQ + r) * CH + c;
            v = g_Qp[idx] + g_Qp[BATCH*RQ*CH + idx]
              + g_Qp[2*BATCH*RQ*CH + idx] + g_Qp[3*BATCH*RQ*CH + idx];
        }
        sQ[r * QSTR + c] = __float2bfloat16(v);
    }
    __syncthreads();

    // ---- hoist Q fragments (loop-invariant) ----
    uint32_t qf[2][6][4];
    #pragma unroll
    for (int i = 0; i < 6; ++i) {
        ldm_x4(qf[0][i][0], qf[0][i][1], qf[0][i][2], qf[0][i][3],
               uQ + (((lane & 15)     ) * QSTR + i * 16 + (lane >> 4) * 8) * 2);
        ldm_x4(qf[1][i][0], qf[1][i][1], qf[1][i][2], qf[1][i][3],
               uQ + ((16 + (lane & 15)) * QSTR + i * 16 + (lane >> 4) * 8) * 2);
    }

    float runM[4], runL[4];
    #pragma unroll
    for (int j = 0; j < 4; ++j) { runM[j] = -1e30f; runL[j] = 0.f; }

    float oacc[2][12][4];
    #pragma unroll
    for (int mt = 0; mt < 2; ++mt)
        #pragma unroll
        for (int j = 0; j < 12; ++j)
            #pragma unroll
            for (int e = 0; e < 4; ++e) oacc[mt][j][e] = 0.f;

    for (int t = 0; t < TILES_PER; ++t) {
        CP_WAIT0();
        __syncthreads();   // staging tile t landed; sX fully consumed by all warps

        // ---- convert staging fp32 -> bf16 sX ----
        #pragma unroll
        for (int r = 0; r < 12; ++r) {
            const int i = tid + 256 * r;
            const int c = i >> 5, n4 = (i & 31) << 2;
            float4 v = *reinterpret_cast<const float4*>(&sXf[c * FSTR + n4]);
            uint2 pk2;
            pk2.x = pack_bf16(v.x, v.y);
            pk2.y = pack_bf16(v.z, v.w);
            *reinterpret_cast<uint2*>(&sX[c * XSTR + n4]) = pk2;
        }
        __syncthreads();   // sX ready; sXf free

        // ---- prefetch tile t+1 (overlaps all compute below) ----
        if (t + 1 < TILES_PER) {
            const float* xt = xb + (t + 1) * TILE;
            #pragma unroll
            for (int r = 0; r < 12; ++r) {
                const int i = tid + 256 * r;
                const int c = i >> 5, n4 = (i & 31) << 2;
                cpasync16(uXf + (c * FSTR + n4) * 4, xt + (size_t)c * HW + n4);
            }
        }
        CP_COMMIT();

        // ---- scores: warp's 16 spatial cols, sc[mt][nt][4] ----
        float sc[2][2][4];
        #pragma unroll
        for (int mt = 0; mt < 2; ++mt)
            #pragma unroll
            for (int nt = 0; nt < 2; ++nt)
                #pragma unroll
                for (int e = 0; e < 4; ++e) sc[mt][nt][e] = 0.f;

        #pragma unroll
        for (int i = 0; i < 6; ++i) {
            uint32_t bfr[4];
            const int grp = lane >> 3;
            const int row = i * 16 + (grp & 1) * 8 + (lane & 7);
            const int col = 16 * warp + (grp >> 1) * 8;
            ldm_x4_t(bfr[0], bfr[1], bfr[2], bfr[3], uX + (row * XSTR + col) * 2);
            mma16816(sc[0][0], qf[0][i], bfr[0], bfr[1]);
            mma16816(sc[0][1], qf[0][i], bfr[2], bfr[3]);
            mma16816(sc[1][0], qf[1][i], bfr[0], bfr[1]);
            mma16816(sc[1][1], qf[1][i], bfr[2], bfr[3]);
        }

        // ---- warp-partial row max -> smem ----
        float mp[4];
        #pragma unroll
        for (int mt = 0; mt < 2; ++mt)
            #pragma unroll
            for (int hl = 0; hl < 2; ++hl) {
                float m = fmaxf(fmaxf(sc[mt][0][hl*2], sc[mt][0][hl*2+1]),
                                fmaxf(sc[mt][1][hl*2], sc[mt][1][hl*2+1]));
                m = fmaxf(m, __shfl_xor_sync(0xffffffffu, m, 1));
                m = fmaxf(m, __shfl_xor_sync(0xffffffffu, m, 2));
                mp[mt*2 + hl] = m;
            }
        if (tig == 0) {
            #pragma unroll
            for (int j = 0; j < 4; ++j) sMax[warp * 32 + g + 8*j] = mp[j];
        }
        __syncthreads();

        // ---- global max, alpha, exp in place (sc -> p), row sums ----
        float newM[4], alpha[4];
        #pragma unroll
        for (int j = 0; j < 4; ++j) {
            float m = runM[j];
            #pragma unroll
            for (int w = 0; w < 8; ++w) m = fmaxf(m, sMax[w * 32 + g + 8*j]);
            newM[j] = m;
            alpha[j] = __expf(runM[j] - m);
            runM[j] = m;
        }
        float rs[4] = {0.f, 0.f, 0.f, 0.f};
        #pragma unroll
        for (int mt = 0; mt < 2; ++mt)
            #pragma unroll
            for (int nt = 0; nt < 2; ++nt)
                #pragma unroll
                for (int hl = 0; hl < 2; ++hl) {
                    const int j = mt*2 + hl;
                    float p0 = __expf(sc[mt][nt][hl*2]   - newM[j]);
                    float p1 = __expf(sc[mt][nt][hl*2+1] - newM[j]);
                    sc[mt][nt][hl*2]   = p0;
                    sc[mt][nt][hl*2+1] = p1;
                    rs[j] += p0 + p1;
                }
        #pragma unroll
        for (int j = 0; j < 4; ++j) {
            rs[j] += __shfl_xor_sync(0xffffffffu, rs[j], 1);
            rs[j] += __shfl_xor_sync(0xffffffffu, rs[j], 2);
        }
        if (tig == 0) {
            #pragma unroll
            for (int j = 0; j < 4; ++j) sSum[warp * 32 + g + 8*j] = rs[j];
        }
        __syncthreads();

        #pragma unroll
        for (int j = 0; j < 4; ++j) {
            float sm = 0.f;
            #pragma unroll
            for (int w = 0; w < 8; ++w) sm += sSum[w * 32 + g + 8*j];
            runL[j] = runL[j] * alpha[j] + sm;
        }

        // ---- P A-fragments directly from score registers ----
        uint32_t pk[2][4];
        #pragma unroll
        for (int mt = 0; mt < 2; ++mt) {
            pk[mt][0] = pack_bf16(sc[mt][0][0], sc[mt][0][1]);  // (g,     k 2tig)
            pk[mt][1] = pack_bf16(sc[mt][0][2], sc[mt][0][3]);  // (g+8,   k 2tig)
            pk[mt][2] = pack_bf16(sc[mt][1][0], sc[mt][1][1]);  // (g,     k 2tig+8)
            pk[mt][3] = pack_bf16(sc[mt][1][2], sc[mt][1][3]);  // (g+8,   k 2tig+8)
        }

        // ---- rescale O, then PV over warp's k16 slice, full 96 channels ----
        #pragma unroll
        for (int mt = 0; mt < 2; ++mt) {
            const float a0v = alpha[2*mt], a1v = alpha[2*mt + 1];
            #pragma unroll
            for (int j = 0; j < 12; ++j) {
                oacc[mt][j][0] *= a0v; oacc[mt][j][1] *= a0v;
                oacc[mt][j][2] *= a1v; oacc[mt][j][3] *= a1v;
            }
        }
        #pragma unroll
        for (int u = 0; u < 6; ++u) {
            uint32_t m0, m1, m2, m3;
            const int grp = lane >> 3;
            const int row = 16 * u + (grp >> 1) * 8 + (lane & 7);   // channel
            const int col = 16 * warp + (grp & 1) * 8;              // spatial k
            ldm_x4(m0, m1, m2, m3, uX + (row * XSTR + col) * 2);
            mma16816(oacc[0][2*u],     pk[0], m0, m1);
            mma16816(oacc[0][2*u + 1], pk[0], m2, m3);
            mma16816(oacc[1][2*u],     pk[1], m0, m1);
            mma16816(oacc[1][2*u + 1], pk[1], m2, m3);
        }
    }

    // ---- epilogue: cross-warp O reduction, then write partials ----
    __syncthreads();   // all PV reads of sX done; overlay sOr
    {
        float* my = sOr + warp * WSTR;
        #pragma unroll
        for (int mt = 0; mt < 2; ++mt)
            #pragma unroll
            for (int j = 0; j < 12; ++j) {
                const int r0 = 16*mt + g, c0 = 8*j + 2*tig;
                my[r0 * OSTR + c0]       = oacc[mt][j][0];
                my[r0 * OSTR + c0 + 1]   = oacc[mt][j][1];
                my[(r0+8) * OSTR + c0]     = oacc[mt][j][2];
                my[(r0+8) * OSTR + c0 + 1] = oacc[mt][j][3];
            }
    }
    __syncthreads();

    const int base = (b * SPLITS + s) * RQ;
    for (int i = tid; i < RQ * CH; i += 256) {
        const int r = i / CH, c = i - r * CH;
        float sum = 0.f;
        #pragma unroll
        for (int w = 0; w < 8; ++w) sum += sOr[w * WSTR + r * OSTR + c];
        g_Ox[(base + r) * CH + c] = sum;
    }
    if (warp == 0 && tig == 0) {
        #pragma unroll
        for (int j = 0; j < 3; ++j) {
            const int r = g + 8*j;       // 0..23
            g_Mx[base + r] = runM[j];
            g_Lx[base + r] = runL[j];
        }
    }
}

// ---------------------------------------------------------------------------
// Kernel 3: combine split partials + output projection + residual.
// ---------------------------------------------------------------------------
__global__ __launch_bounds__(DMODEL) void combine_proj_kernel(
    const float* __restrict__ z, const float* __restrict__ Wo,
    const float* __restrict__ bo, float* __restrict__ out)
{
    __shared__ float sOf[RQ * CH];
    __shared__ float sW[RQ * 16];
    __shared__ float sLi[RQ];
    const int b = blockIdx.x, tid = threadIdx.x;

    if (tid < RQ) {
        const int q = tid;
        float Mg = -1e30f;
        for (int s = 0; s < SPLITS; ++s)
            Mg = fmaxf(Mg, g_Mx[(b * SPLITS + s) * RQ + q]);
        float L = 0.f;
        for (int s = 0; s < SPLITS; ++s) {
            const float w = __expf(g_Mx[(b * SPLITS + s) * RQ + q] - Mg);
            sW[q * 16 + s] = w;
            L += w * g_Lx[(b * SPLITS + s) * RQ + q];
        }
        sLi[q] = 1.f / L;
    }
    __syncthreads();

    for (int o = tid; o < RQ * CH; o += DMODEL) {
        const int q = o / CH, c = o - q * CH;
        float a = 0.f;
        #pragma unroll
        for (int s = 0; s < SPLITS; ++s)
            a = fmaf(sW[q * 16 + s], g_Ox[((b * SPLITS + s) * RQ + q) * CH + c], a);
        sOf[o] = a * sLi[q];
    }
    __syncthreads();

    float accv[MTOK];
    #pragma unroll
    for (int m = 0; m < MTOK; ++m)
        accv[m] = z[(b * MTOK + m) * DMODEL + tid] + bo[tid];

    for (int h = 0; h < HEADS; ++h) {
        #pragma unroll 4
        for (int c = 0; c < CH; ++c) {
            const float w = Wo[(h * CH + c) * DMODEL + tid];
            #pragma unroll
            for (int m = 0; m < MTOK; ++m)
                accv[m] = fmaf(sOf[(h * MTOK + m) * CH + c], w, accv[m]);
        }
    }
    #pragma unroll
    for (int m = 0; m < MTOK; ++m)
        out[(b * MTOK + m) * DMODEL + tid] = accv[m];
}

// ---------------------------------------------------------------------------
extern "C" void kernel_launch(void* const* d_in, const int* in_sizes, int n_in,
                              void* d_out, int out_size)
{
    const float* x  = (const float*)d_in[0];
    const float* z  = (const float*)d_in[1];
    const float* Wq = (const float*)d_in[2];
    const float* bq = (const float*)d_in[3];
    const float* Wo = (const float*)d_in[4];
    const float* bo = (const float*)d_in[5];
    float* out = (float*)d_out;

    cudaFuncSetAttribute(attn_partial_kernel,
                         cudaFuncAttributeMaxDynamicSharedMemorySize, SMEM_TOT);

    qproj_kernel<<<dim3(BATCH, 4), QDIM>>>(z, Wq, bq);
    attn_partial_kernel<<<dim3(SPLITS, BATCH), 256, SMEM_TOT>>>(x);
    combine_proj_kernel<<<BATCH, DMODEL>>>(z, Wo, bo, out);
}